// round 11
// baseline (speedup 1.0000x reference)
#include <cuda_runtime.h>
#include <cuda_bf16.h>
#include <cuda_fp16.h>
#include <cstdint>
#include <cstddef>

// ---------------- problem constants ----------------------------------------
#define BB 256
#define SS 256
#define EE 384
#define HH 6
#define DH 64
#define FF 1536
#define MM (BB*SS)                  // 65536
#define BHSD ((size_t)BB*HH*SS*DH)  // 25,165,824

// ---------------- scratch (device globals; no allocation allowed) ----------
__device__ __half  g_hln[(size_t)MM*EE];   // LN1 out fp16
__device__ __half  g_qkv[3*BHSD];          // q,k,v fp16 [3][B,H,S,D]
__device__ __half  g_o[(size_t)MM*EE];     // attention out fp16
__device__ float   g_x1[(size_t)MM*EE];    // x + proj (fp32)
__device__ __half  g_h2[(size_t)MM*EE];    // LN2 out fp16
__device__ __half  g_mid[(size_t)MM*FF];   // relu(ffn1) fp16
__device__ __half  g_wqkv[(size_t)1152*384];
__device__ __half  g_wp[(size_t)384*384];
__device__ __half  g_w1[(size_t)1536*384];
__device__ __half  g_w2[(size_t)384*1536];

// ---------------- helpers ---------------------------------------------------
__device__ __forceinline__ uint32_t smem_to_u32(const void* p) {
    uint32_t a;
    asm("{ .reg .u64 t; cvta.to.shared.u64 t, %1; cvt.u32.u64 %0, t; }"
        : "=r"(a) : "l"(p));
    return a;
}

#define CP_ASYNC16(sm, gp) \
    asm volatile("cp.async.cg.shared.global [%0], [%1], 16;" \
        :: "r"((uint32_t)(sm)), "l"(gp) : "memory")
#define CP_COMMIT() asm volatile("cp.async.commit_group;" ::: "memory")
#define CP_WAIT1()  asm volatile("cp.async.wait_group 1;" ::: "memory")

__device__ __forceinline__ void ldsm_x4(uint32_t* r, uint32_t addr) {
    asm volatile("ldmatrix.sync.aligned.m8n8.x4.shared.b16 {%0,%1,%2,%3}, [%4];"
        : "=r"(r[0]), "=r"(r[1]), "=r"(r[2]), "=r"(r[3]) : "r"(addr));
}
// fp16-accumulator HMMA (2x rate hypothesis on sm_103 legacy path)
__device__ __forceinline__ void mma16816h(uint32_t* d, const uint32_t* a, const uint32_t* b) {
    asm volatile(
        "mma.sync.aligned.m16n8k16.row.col.f16.f16.f16.f16 "
        "{%0,%1}, {%2,%3,%4,%5}, {%6,%7}, {%0,%1};"
        : "+r"(d[0]), "+r"(d[1])
        : "r"(a[0]), "r"(a[1]), "r"(a[2]), "r"(a[3]), "r"(b[0]), "r"(b[1]));
}

// ---------------- weight packing (fp16) -------------------------------------
__global__ void pack_qkv_kernel(const float* __restrict__ Wq,
                                const float* __restrict__ Wk,
                                const float* __restrict__ Wv) {
    int idx = blockIdx.x * 256 + threadIdx.x;
    if (idx >= 1152 * 384) return;
    int n = idx / 384, k = idx - n * 384;
    int m3 = n / 384;
    int rem = n - m3 * 384;
    int h = rem >> 6, d = rem & 63;
    const float* W = (m3 == 0) ? Wq : (m3 == 1) ? Wk : Wv;
    g_wqkv[idx] = __float2half(W[((size_t)h * 384 + k) * 64 + d]);
}

// B[n,k] = src[k*ldn + n]
__global__ void pack_gen_kernel(const float* __restrict__ src, __half* dst,
                                int N, int K, int ldn) {
    int idx = blockIdx.x * 256 + threadIdx.x;
    if (idx >= N * K) return;
    int n = idx / K, k = idx - n * K;
    dst[idx] = __float2half(src[(size_t)k * ldn + n]);
}

// ---------------- LayerNorm: one WARP per row (no block barriers) -----------
__global__ void ln_kernel(const float* __restrict__ in,
                          const float* __restrict__ gamma,
                          const float* __restrict__ beta,
                          __half* __restrict__ out) {
    int wid = threadIdx.x >> 5;
    int lane = threadIdx.x & 31;
    int row = blockIdx.x * 4 + wid;
    const float* r = in + (size_t)row * EE;
    float4 v[3];
    #pragma unroll
    for (int j = 0; j < 3; j++)
        v[j] = *(const float4*)(r + lane * 4 + j * 128);
    float s = v[0].x + v[0].y + v[0].z + v[0].w
            + v[1].x + v[1].y + v[1].z + v[1].w
            + v[2].x + v[2].y + v[2].z + v[2].w;
    #pragma unroll
    for (int o = 16; o; o >>= 1) s += __shfl_xor_sync(0xffffffffu, s, o);
    float mu = s * (1.0f / 384.0f);
    float vs = 0.f;
    #pragma unroll
    for (int j = 0; j < 3; j++) {
        v[j].x -= mu; v[j].y -= mu; v[j].z -= mu; v[j].w -= mu;
        vs += v[j].x * v[j].x + v[j].y * v[j].y + v[j].z * v[j].z + v[j].w * v[j].w;
    }
    #pragma unroll
    for (int o = 16; o; o >>= 1) vs += __shfl_xor_sync(0xffffffffu, vs, o);
    float rstd = rsqrtf(vs * (1.0f / 384.0f) + 1e-5f);
    __half* w = out + (size_t)row * EE;
    #pragma unroll
    for (int j = 0; j < 3; j++) {
        int c = lane * 4 + j * 128;
        float4 gg = *(const float4*)(gamma + c);
        float4 bb = *(const float4*)(beta + c);
        __half2 h0 = __floats2half2_rn(v[j].x * rstd * gg.x + bb.x,
                                       v[j].y * rstd * gg.y + bb.y);
        __half2 h1 = __floats2half2_rn(v[j].z * rstd * gg.z + bb.z,
                                       v[j].w * rstd * gg.w + bb.w);
        *(__half2*)(w + c) = h0;
        *(__half2*)(w + c + 2) = h1;
    }
}

// ---------------- mma.sync GEMM (fp16 in, fp16 chunk-accum -> fp32) --------
// D[M,N] = A[M,K] . B[N,K]^T
// modes: 0 = QKV scatter fp16; 1 = resid + D + bias (fp32);
//        2 = relu(D+bias) -> fp16; 3 = same as 1 (out to d_out)
// Tile: 128x64, BK=64, 3-stage cp.async, 8 warps, warp tile 32x32.
// fp16 accumulate within one BK=64 chunk, folded to fp32 per chunk.
#define STAGE_BYTES 27648   // A: 128*144, B: 64*144
#define GSMEM (3 * STAGE_BYTES)

__global__ __launch_bounds__(256, 2)
void mma_gemm(const __half* __restrict__ A, const __half* __restrict__ B,
              void* outp, const float* __restrict__ bias,
              const float* __restrict__ resid, int K, int N, int mode) {
    extern __shared__ __align__(128) uint8_t dsm[];
    const uint32_t sb = smem_to_u32(dsm);
    const int tid = threadIdx.x;
    const int lane = tid & 31;
    const int wid = tid >> 5;
    const int wm = wid >> 1;        // 0..3  (32-row slabs)
    const int wn = wid & 1;         // 0..1  (32-col slabs)
    const int m0 = blockIdx.y * 128;
    const int n0 = blockIdx.x * 64;
    const int CT = K >> 6;          // K chunks of 64

    const int rr = tid >> 3;        // 0..31
    const int qq = tid & 7;         // 16B col chunk

    float acc[2][4][4];
    #pragma unroll
    for (int i = 0; i < 2; i++)
        #pragma unroll
        for (int j = 0; j < 4; j++)
            #pragma unroll
            for (int t = 0; t < 4; t++) acc[i][j][t] = 0.0f;

    #define LOAD_STAGE(c) do { \
        int s_ = (c) % 3; \
        int k0_ = (c) << 6; \
        uint32_t sa_ = sb + s_ * STAGE_BYTES; \
        uint32_t sbm_ = sa_ + 18432u; \
        _Pragma("unroll") \
        for (int i_ = 0; i_ < 4; ++i_) { \
            int r_ = rr + i_ * 32; \
            CP_ASYNC16(sa_ + r_ * 144 + qq * 16, A + (size_t)(m0 + r_) * K + k0_ + qq * 8); \
        } \
        _Pragma("unroll") \
        for (int i_ = 0; i_ < 2; ++i_) { \
            int r_ = rr + i_ * 32; \
            CP_ASYNC16(sbm_ + r_ * 144 + qq * 16, B + (size_t)(n0 + r_) * K + k0_ + qq * 8); \
        } \
    } while (0)

    LOAD_STAGE(0); CP_COMMIT();
    LOAD_STAGE(1); CP_COMMIT();

    const uint32_t a_row  = (uint32_t)(wm * 32 + (lane & 15));
    const uint32_t a_coff = (uint32_t)((lane >> 4) * 16);
    const uint32_t b_row  = (uint32_t)(wn * 32 + (lane & 15));
    const uint32_t b_coff = (uint32_t)((lane >> 4) * 16);

    for (int c = 0; c < CT; ++c) {
        CP_WAIT1();
        __syncthreads();   // stage c resident; stage c-1 LDSM reads done
        if (c + 2 < CT) { LOAD_STAGE(c + 2); }
        CP_COMMIT();
        uint32_t sa = sb + (c % 3) * STAGE_BYTES;
        uint32_t sbm = sa + 18432u;
        uint32_t hacc[2][4][2];
        #pragma unroll
        for (int mt = 0; mt < 2; ++mt)
            #pragma unroll
            for (int nt = 0; nt < 4; ++nt) { hacc[mt][nt][0] = 0u; hacc[mt][nt][1] = 0u; }
        #pragma unroll
        for (int ks = 0; ks < 4; ++ks) {
            uint32_t afr[2][4], bq[2][4];
            #pragma unroll
            for (int mt = 0; mt < 2; ++mt)
                ldsm_x4(afr[mt], sa + (a_row + mt * 16) * 144 + ks * 32 + a_coff);
            #pragma unroll
            for (int np = 0; np < 2; ++np)
                ldsm_x4(bq[np], sbm + (b_row + np * 16) * 144 + ks * 32 + b_coff);
            #pragma unroll
            for (int mt = 0; mt < 2; ++mt)
                #pragma unroll
                for (int nt = 0; nt < 4; ++nt) {
                    uint32_t bb[2];
                    bb[0] = bq[nt >> 1][(nt & 1)];
                    bb[1] = bq[nt >> 1][(nt & 1) + 2];
                    mma16816h(hacc[mt][nt], afr[mt], bb);
                }
        }
        // fold fp16 chunk accumulators into fp32
        #pragma unroll
        for (int mt = 0; mt < 2; ++mt)
            #pragma unroll
            for (int nt = 0; nt < 4; ++nt) {
                float2 f0 = __half22float2(*reinterpret_cast<__half2*>(&hacc[mt][nt][0]));
                float2 f1 = __half22float2(*reinterpret_cast<__half2*>(&hacc[mt][nt][1]));
                acc[mt][nt][0] += f0.x; acc[mt][nt][1] += f0.y;
                acc[mt][nt][2] += f1.x; acc[mt][nt][3] += f1.y;
            }
    }

    // ---- epilogue: direct stores ----
    #pragma unroll
    for (int mt = 0; mt < 2; ++mt) {
        #pragma unroll
        for (int nt = 0; nt < 4; ++nt) {
            int col = n0 + wn * 32 + nt * 8 + (lane & 3) * 2;
            #pragma unroll
            for (int half_ = 0; half_ < 2; ++half_) {
                int rg = m0 + wm * 32 + mt * 16 + (lane >> 2) + half_ * 8;
                float v0 = acc[mt][nt][half_ * 2 + 0];
                float v1 = acc[mt][nt][half_ * 2 + 1];
                if (mode == 0) {
                    int m3 = col / 384;
                    int rem = col - m3 * 384;
                    int h = rem >> 6, dd = rem & 63;
                    int b = rg >> 8, sq = rg & 255;
                    __half2 val = __floats2half2_rn(v0, v1);
                    *(__half2*)((__half*)outp + (size_t)m3 * BHSD +
                                ((size_t)((b * HH + h) * SS + sq)) * DH + dd) = val;
                } else if (mode == 2) {
                    float s0 = fmaxf(v0 + bias[col], 0.f);
                    float s1 = fmaxf(v1 + bias[col + 1], 0.f);
                    *(__half2*)((__half*)outp + (size_t)rg * FF + col) =
                        __floats2half2_rn(s0, s1);
                } else {
                    float2 rr2 = *(const float2*)(resid + (size_t)rg * N + col);
                    float2 val = make_float2(v0 + bias[col] + rr2.x,
                                             v1 + bias[col + 1] + rr2.y);
                    *(float2*)((float*)outp + (size_t)rg * N + col) = val;
                }
            }
        }
    }
}

// ---------------- attention: online softmax, fp16 in/out, fp32 math --------
// SMSP-balanced query mapping: warp w -> query block (w<4 ? w : 11-w).
__global__ __launch_bounds__(256, 1)
void attn_kernel() {
    extern __shared__ float attnsm[];
    float* Ksm = attnsm;
    float* Vsm = attnsm + SS * DH;
    int bh = blockIdx.x;
    int b = bh / HH;
    int h = bh - b * HH;
    int tid = threadIdx.x;
    int lane = tid & 31;
    int wid = tid >> 5;

    const __half* qb = g_qkv + (size_t)bh * SS * DH;
    const __half* kb = g_qkv + BHSD + (size_t)bh * SS * DH;
    const __half* vb = g_qkv + 2 * BHSD + (size_t)bh * SS * DH;

    // load K,V (fp16 global) -> fp32 smem
    const uint4* k8 = (const uint4*)kb;   // 8 halves per uint4
    const uint4* v8 = (const uint4*)vb;
    #pragma unroll
    for (int i = 0; i < (SS * DH / 8) / 256; i++) {
        int idx = tid + i * 256;
        uint4 kk = k8[idx];
        uint4 vv = v8[idx];
        const __half2* kp = (const __half2*)&kk;
        const __half2* vp = (const __half2*)&vv;
        #pragma unroll
        for (int j = 0; j < 4; j++) {
            float2 kf = __half22float2(kp[j]);
            float2 vf = __half22float2(vp[j]);
            Ksm[idx * 8 + j * 2 + 0] = kf.x;
            Ksm[idx * 8 + j * 2 + 1] = kf.y;
            Vsm[idx * 8 + j * 2 + 0] = vf.x;
            Vsm[idx * 8 + j * 2 + 1] = vf.y;
        }
    }
    __syncthreads();

    int qblk = (wid < 4) ? wid : 11 - wid;
    int s = qblk * 32 + lane;
    float4 q[16];
    {
        const uint4* qr = (const uint4*)(qb + (size_t)s * DH);
        #pragma unroll
        for (int i = 0; i < 8; i++) {
            uint4 qq = qr[i];
            const __half2* qp = (const __half2*)&qq;
            float2 f0 = __half22float2(qp[0]);
            float2 f1 = __half22float2(qp[1]);
            float2 f2 = __half22float2(qp[2]);
            float2 f3 = __half22float2(qp[3]);
            q[i * 2 + 0] = make_float4(f0.x, f0.y, f1.x, f1.y);
            q[i * 2 + 1] = make_float4(f2.x, f2.y, f3.x, f3.y);
        }
    }

    const float scale = 0.125f;
    float mx = -1e30f, sum = 0.0f;
    float4 o[16];
    #pragma unroll
    for (int i = 0; i < 16; i++) o[i] = make_float4(0.f, 0.f, 0.f, 0.f);

    for (int t = 0; t <= s; t++) {
        const float4* kr = (const float4*)(Ksm + t * DH);
        float acc = 0.0f;
        #pragma unroll
        for (int i = 0; i < 16; i++) {
            float4 kk = kr[i];
            acc = fmaf(q[i].x, kk.x, acc);
            acc = fmaf(q[i].y, kk.y, acc);
            acc = fmaf(q[i].z, kk.z, acc);
            acc = fmaf(q[i].w, kk.w, acc);
        }
        float sc = acc * scale;
        float p;
        if (sc > mx) {
            float corr = __expf(mx - sc);
            sum *= corr;
            #pragma unroll
            for (int i = 0; i < 16; i++) {
                o[i].x *= corr; o[i].y *= corr; o[i].z *= corr; o[i].w *= corr;
            }
            mx = sc;
            p = 1.0f;
        } else {
            p = __expf(sc - mx);
        }
        sum += p;
        const float4* vr = (const float4*)(Vsm + t * DH);
        #pragma unroll
        for (int i = 0; i < 16; i++) {
            float4 vv = vr[i];
            o[i].x = fmaf(p, vv.x, o[i].x);
            o[i].y = fmaf(p, vv.y, o[i].y);
            o[i].z = fmaf(p, vv.z, o[i].z);
            o[i].w = fmaf(p, vv.w, o[i].w);
        }
    }
    float inv = 1.0f / sum;
    __half* ow = g_o + (size_t)(b * SS + s) * EE + h * DH;
    #pragma unroll
    for (int i = 0; i < 16; i++) {
        *(__half2*)(ow + i * 4 + 0) = __floats2half2_rn(o[i].x * inv, o[i].y * inv);
        *(__half2*)(ow + i * 4 + 2) = __floats2half2_rn(o[i].z * inv, o[i].w * inv);
    }
}

// ---------------- host -----------------------------------------------------
extern "C" void kernel_launch(void* const* d_in, const int* in_sizes, int n_in,
                              void* d_out, int out_size) {
    const float* x   = (const float*)d_in[0];
    const float* Wq  = (const float*)d_in[1];
    const float* Wk  = (const float*)d_in[2];
    const float* Wv  = (const float*)d_in[3];
    const float* Wp  = (const float*)d_in[4];
    const float* bp  = (const float*)d_in[5];
    const float* W1  = (const float*)d_in[6];
    const float* b1  = (const float*)d_in[7];
    const float* W2  = (const float*)d_in[8];
    const float* b2  = (const float*)d_in[9];
    const float* g1  = (const float*)d_in[10];
    const float* be1 = (const float*)d_in[11];
    const float* g2  = (const float*)d_in[12];
    const float* be2 = (const float*)d_in[13];
    float* out = (float*)d_out;

    void *hlnv, *qkvv, *ov, *x1v, *h2v, *midv, *wqkvv, *wpv, *w1v, *w2v;
    cudaGetSymbolAddress(&hlnv,  g_hln);
    cudaGetSymbolAddress(&qkvv,  g_qkv);
    cudaGetSymbolAddress(&ov,    g_o);
    cudaGetSymbolAddress(&x1v,   g_x1);
    cudaGetSymbolAddress(&h2v,   g_h2);
    cudaGetSymbolAddress(&midv,  g_mid);
    cudaGetSymbolAddress(&wqkvv, g_wqkv);
    cudaGetSymbolAddress(&wpv,   g_wp);
    cudaGetSymbolAddress(&w1v,   g_w1);
    cudaGetSymbolAddress(&w2v,   g_w2);

    __half* hln  = (__half*)hlnv;
    __half* qkv  = (__half*)qkvv;
    __half* o    = (__half*)ov;
    float*  x1   = (float*)x1v;
    __half* h2   = (__half*)h2v;
    __half* mid  = (__half*)midv;
    __half* wqkv = (__half*)wqkvv;
    __half* wp   = (__half*)wpv;
    __half* w1   = (__half*)w1v;
    __half* w2   = (__half*)w2v;

    cudaFuncSetAttribute(mma_gemm, cudaFuncAttributeMaxDynamicSharedMemorySize, GSMEM);
    cudaFuncSetAttribute(attn_kernel, cudaFuncAttributeMaxDynamicSharedMemorySize,
                         2 * SS * DH * (int)sizeof(float));

    // weight packing (fp16)
    pack_qkv_kernel<<<(1152 * 384 + 255) / 256, 256>>>(Wq, Wk, Wv);
    pack_gen_kernel<<<(384 * 384 + 255) / 256, 256>>>(Wp, wp, 384, 384, 384);
    pack_gen_kernel<<<(1536 * 384 + 255) / 256, 256>>>(W1, w1, 1536, 384, 1536);
    pack_gen_kernel<<<(384 * 1536 + 255) / 256, 256>>>(W2, w2, 384, 1536, 384);
    // LN1 (warp-per-row)
    ln_kernel<<<MM / 4, 128>>>(x, g1, be1, hln);
    // QKV projection (scatter into [3][B,H,S,D] fp16)
    mma_gemm<<<dim3(18, 512), 256, GSMEM>>>(
        hln, wqkv, qkv, nullptr, nullptr, 384, 1152, 0);
    // causal attention
    attn_kernel<<<BB * HH, 256, 2 * SS * DH * sizeof(float)>>>();
    // out projection + residual: x1 = x + o@Wp + bp
    mma_gemm<<<dim3(6, 512), 256, GSMEM>>>(
        o, wp, x1, bp, x, 384, 384, 1);
    // LN2 (warp-per-row)
    ln_kernel<<<MM / 4, 128>>>(x1, g2, be2, h2);
    // FFN1 + relu -> fp16
    mma_gemm<<<dim3(24, 512), 256, GSMEM>>>(
        h2, w1, mid, b1, nullptr, 384, 1536, 2);
    // FFN2 + residual -> out
    mma_gemm<<<dim3(6, 512), 256, GSMEM>>>(
        mid, w2, out, b2, x1, 1536, 384, 3);
}

// round 17
// speedup vs baseline: 1.7945x; 1.7945x over previous
#include <cuda_runtime.h>
#include <cuda_bf16.h>
#include <cuda_fp16.h>
#include <cstdint>
#include <cstddef>

// ---------------- problem constants ----------------------------------------
#define BB 256
#define SS 256
#define EE 384
#define HH 6
#define DH 64
#define FF 1536
#define MM (BB*SS)                  // 65536
#define BHSD ((size_t)BB*HH*SS*DH)  // 25,165,824

// ---------------- scratch (device globals; no allocation allowed) ----------
__device__ __half  g_hln[(size_t)MM*EE];   // LN1 out fp16
__device__ __half  g_qkv[3*BHSD];          // q,k,v fp16 [3][B,H,S,D]
__device__ __half  g_o[(size_t)MM*EE];     // attention out fp16
__device__ float   g_x1[(size_t)MM*EE];    // x + proj (fp32)
__device__ __half  g_h2[(size_t)MM*EE];    // LN2 out fp16
__device__ __half  g_mid[(size_t)MM*FF];   // relu(ffn1) fp16
__device__ __half  g_wqkv[(size_t)1152*384];
__device__ __half  g_wp[(size_t)384*384];
__device__ __half  g_w1[(size_t)1536*384];
__device__ __half  g_w2[(size_t)384*1536];

// ---------------- helpers ---------------------------------------------------
__device__ __forceinline__ uint32_t smem_to_u32(const void* p) {
    uint32_t a;
    asm("{ .reg .u64 t; cvta.to.shared.u64 t, %1; cvt.u32.u64 %0, t; }"
        : "=r"(a) : "l"(p));
    return a;
}

#define CP_ASYNC16(sm, gp) \
    asm volatile("cp.async.cg.shared.global [%0], [%1], 16;" \
        :: "r"((uint32_t)(sm)), "l"(gp) : "memory")
#define CP_COMMIT() asm volatile("cp.async.commit_group;" ::: "memory")
#define CP_WAIT2()  asm volatile("cp.async.wait_group 2;" ::: "memory")

__device__ __forceinline__ void ldsm_x4(uint32_t* r, uint32_t addr) {
    asm volatile("ldmatrix.sync.aligned.m8n8.x4.shared.b16 {%0,%1,%2,%3}, [%4];"
        : "=r"(r[0]), "=r"(r[1]), "=r"(r[2]), "=r"(r[3]) : "r"(addr));
}
__device__ __forceinline__ void ldsm_x4t(uint32_t* r, uint32_t addr) {
    asm volatile("ldmatrix.sync.aligned.m8n8.x4.trans.shared.b16 {%0,%1,%2,%3}, [%4];"
        : "=r"(r[0]), "=r"(r[1]), "=r"(r[2]), "=r"(r[3]) : "r"(addr));
}
__device__ __forceinline__ void ldsm_x2(uint32_t* r, uint32_t addr) {
    asm volatile("ldmatrix.sync.aligned.m8n8.x2.shared.b16 {%0,%1}, [%2];"
        : "=r"(r[0]), "=r"(r[1]) : "r"(addr));
}
__device__ __forceinline__ void mma16816(float* d, const uint32_t* a, const uint32_t* b) {
    asm volatile(
        "mma.sync.aligned.m16n8k16.row.col.f32.f16.f16.f32 "
        "{%0,%1,%2,%3}, {%4,%5,%6,%7}, {%8,%9}, {%0,%1,%2,%3};"
        : "+f"(d[0]), "+f"(d[1]), "+f"(d[2]), "+f"(d[3])
        : "r"(a[0]), "r"(a[1]), "r"(a[2]), "r"(a[3]), "r"(b[0]), "r"(b[1]));
}

// fast 2^x on fma/alu pipes (x <= ~+6; clamped below -80 -> ~0)
__device__ __forceinline__ float exp2p(float x) {
    x = fmaxf(x, -80.f);
    float z = x + 12582912.f;              // round-to-nearest-int trick
    int i = __float_as_int(z) - 0x4B400000;
    float f = x - (z - 12582912.f);        // f in [-0.5, 0.5]
    float p = 0.0013333558f;
    p = fmaf(p, f, 0.009618129f);
    p = fmaf(p, f, 0.05550411f);
    p = fmaf(p, f, 0.2402265f);
    p = fmaf(p, f, 0.6931472f);
    p = fmaf(p, f, 1.0f);
    return __int_as_float(__float_as_int(p) + (i << 23));
}

// ---------------- weight packing (fp16) -------------------------------------
__global__ void pack_qkv_kernel(const float* __restrict__ Wq,
                                const float* __restrict__ Wk,
                                const float* __restrict__ Wv) {
    int idx = blockIdx.x * 256 + threadIdx.x;
    if (idx >= 1152 * 384) return;
    int n = idx / 384, k = idx - n * 384;
    int m3 = n / 384;
    int rem = n - m3 * 384;
    int h = rem >> 6, d = rem & 63;
    const float* W = (m3 == 0) ? Wq : (m3 == 1) ? Wk : Wv;
    g_wqkv[idx] = __float2half(W[((size_t)h * 384 + k) * 64 + d]);
}

// B[n,k] = src[k*ldn + n]
__global__ void pack_gen_kernel(const float* __restrict__ src, __half* dst,
                                int N, int K, int ldn) {
    int idx = blockIdx.x * 256 + threadIdx.x;
    if (idx >= N * K) return;
    int n = idx / K, k = idx - n * K;
    dst[idx] = __float2half(src[(size_t)k * ldn + n]);
}

// ---------------- LayerNorm: one WARP per row -------------------------------
__global__ void ln_kernel(const float* __restrict__ in,
                          const float* __restrict__ gamma,
                          const float* __restrict__ beta,
                          __half* __restrict__ out) {
    int wid = threadIdx.x >> 5;
    int lane = threadIdx.x & 31;
    int row = blockIdx.x * 4 + wid;
    const float* r = in + (size_t)row * EE;
    float4 v[3];
    #pragma unroll
    for (int j = 0; j < 3; j++)
        v[j] = *(const float4*)(r + lane * 4 + j * 128);
    float s = v[0].x + v[0].y + v[0].z + v[0].w
            + v[1].x + v[1].y + v[1].z + v[1].w
            + v[2].x + v[2].y + v[2].z + v[2].w;
    #pragma unroll
    for (int o = 16; o; o >>= 1) s += __shfl_xor_sync(0xffffffffu, s, o);
    float mu = s * (1.0f / 384.0f);
    float vs = 0.f;
    #pragma unroll
    for (int j = 0; j < 3; j++) {
        v[j].x -= mu; v[j].y -= mu; v[j].z -= mu; v[j].w -= mu;
        vs += v[j].x * v[j].x + v[j].y * v[j].y + v[j].z * v[j].z + v[j].w * v[j].w;
    }
    #pragma unroll
    for (int o = 16; o; o >>= 1) vs += __shfl_xor_sync(0xffffffffu, vs, o);
    float rstd = rsqrtf(vs * (1.0f / 384.0f) + 1e-5f);
    __half* w = out + (size_t)row * EE;
    #pragma unroll
    for (int j = 0; j < 3; j++) {
        int c = lane * 4 + j * 128;
        float4 gg = *(const float4*)(gamma + c);
        float4 bb = *(const float4*)(beta + c);
        __half2 h0 = __floats2half2_rn(v[j].x * rstd * gg.x + bb.x,
                                       v[j].y * rstd * gg.y + bb.y);
        __half2 h1 = __floats2half2_rn(v[j].z * rstd * gg.z + bb.z,
                                       v[j].w * rstd * gg.w + bb.w);
        *(__half2*)(w + c) = h0;
        *(__half2*)(w + c + 2) = h1;
    }
}

// ---------------- mma.sync GEMM (R9 config: BK=32, fp32 acc) ----------------
#define STAGE_BYTES 20480   // A: 128*80, B: 128*80
#define GSMEM (4 * STAGE_BYTES)

__global__ __launch_bounds__(256, 2)
void mma_gemm(const __half* __restrict__ A, const __half* __restrict__ B,
              void* outp, const float* __restrict__ bias,
              const float* __restrict__ resid, int K, int N, int mode) {
    extern __shared__ __align__(128) uint8_t dsm[];
    const uint32_t sb = smem_to_u32(dsm);
    const int tid = threadIdx.x;
    const int lane = tid & 31;
    const int wid = tid >> 5;
    const int wm = wid >> 2;
    const int wn = wid & 3;
    const int m0 = blockIdx.y * 128;
    const int n0 = blockIdx.x * 128;
    const int CT = K >> 5;

    const int c0 = tid, c1 = tid + 256;
    const int r0 = c0 >> 2, q0 = c0 & 3;
    const int r1 = c1 >> 2, q1 = c1 & 3;

    float acc[4][4][4];
    #pragma unroll
    for (int i = 0; i < 4; i++)
        #pragma unroll
        for (int j = 0; j < 4; j++)
            #pragma unroll
            for (int t = 0; t < 4; t++) acc[i][j][t] = 0.0f;

    #define LOAD_STAGE(c) do { \
        int s_ = (c) & 3; \
        int k0_ = (c) << 5; \
        uint32_t sa = sb + s_ * STAGE_BYTES; \
        uint32_t sbm = sa + 10240; \
        CP_ASYNC16(sa  + r0 * 80 + q0 * 16, A + (size_t)(m0 + r0) * K + k0_ + q0 * 8); \
        CP_ASYNC16(sa  + r1 * 80 + q1 * 16, A + (size_t)(m0 + r1) * K + k0_ + q1 * 8); \
        CP_ASYNC16(sbm + r0 * 80 + q0 * 16, B + (size_t)(n0 + r0) * K + k0_ + q0 * 8); \
        CP_ASYNC16(sbm + r1 * 80 + q1 * 16, B + (size_t)(n0 + r1) * K + k0_ + q1 * 8); \
    } while (0)

    LOAD_STAGE(0); CP_COMMIT();
    LOAD_STAGE(1); CP_COMMIT();
    LOAD_STAGE(2); CP_COMMIT();

    const uint32_t a_row = (uint32_t)(wm * 64 + (lane & 15));
    const uint32_t a_coff = (uint32_t)((lane >> 4) * 8) * 2;
    const uint32_t b_row = (uint32_t)(wn * 32 + (lane & 7));
    const uint32_t b_coff = (uint32_t)(((lane >> 3) & 1) * 8) * 2;

    for (int c = 0; c < CT; ++c) {
        CP_WAIT2();
        __syncthreads();
        if (c + 3 < CT) { LOAD_STAGE(c + 3); }
        CP_COMMIT();
        uint32_t sa = sb + (c & 3) * STAGE_BYTES;
        uint32_t sbm = sa + 10240;
        #pragma unroll
        for (int ks = 0; ks < 2; ++ks) {
            uint32_t afr[4][4], bfr[4][2];
            #pragma unroll
            for (int mt = 0; mt < 4; ++mt)
                ldsm_x4(afr[mt], sa + (a_row + mt * 16) * 80 + ks * 32 + a_coff);
            #pragma unroll
            for (int nt = 0; nt < 4; ++nt)
                ldsm_x2(bfr[nt], sbm + (b_row + nt * 8) * 80 + ks * 32 + b_coff);
            #pragma unroll
            for (int mt = 0; mt < 4; ++mt)
                #pragma unroll
                for (int nt = 0; nt < 4; ++nt)
                    mma16816(acc[mt][nt], afr[mt], bfr[nt]);
        }
    }

    #pragma unroll
    for (int mt = 0; mt < 4; ++mt) {
        #pragma unroll
        for (int nt = 0; nt < 4; ++nt) {
            int col = n0 + wn * 32 + nt * 8 + (lane & 3) * 2;
            #pragma unroll
            for (int half_ = 0; half_ < 2; ++half_) {
                int rg = m0 + wm * 64 + mt * 16 + (lane >> 2) + half_ * 8;
                float v0 = acc[mt][nt][half_ * 2 + 0];
                float v1 = acc[mt][nt][half_ * 2 + 1];
                if (mode == 0) {
                    int m3 = col / 384;
                    int rem = col - m3 * 384;
                    int h = rem >> 6, dd = rem & 63;
                    int b = rg >> 8, sq = rg & 255;
                    __half2 val = __floats2half2_rn(v0, v1);
                    *(__half2*)((__half*)outp + (size_t)m3 * BHSD +
                                ((size_t)((b * HH + h) * SS + sq)) * DH + dd) = val;
                } else if (mode == 2) {
                    float s0 = fmaxf(v0 + bias[col], 0.f);
                    float s1 = fmaxf(v1 + bias[col + 1], 0.f);
                    *(__half2*)((__half*)outp + (size_t)rg * FF + col) =
                        __floats2half2_rn(s0, s1);
                } else {
                    float2 rr2 = *(const float2*)(resid + (size_t)rg * N + col);
                    float2 val = make_float2(v0 + bias[col] + rr2.x,
                                             v1 + bias[col + 1] + rr2.y);
                    *(float2*)((float*)outp + (size_t)rg * N + col) = val;
                }
            }
        }
    }
}

// ---------------- flash attention: tensor-core QK/AV + poly-exp softmax -----
// One CTA per (b,h); 8 warps, warp w owns 32 query rows (qb = w<4?w:11-w).
// Q,K,V fp16 in smem (144B padded rows). S via m16n8k16 (fp32 acc),
// online softmax with exp2 poly on fma pipe, P->fp16 A-frags, AV via
// ldmatrix.trans on V. Causal: per-mt kt bound + diagonal mask.
#define ATTN_SMEM (3 * 36864)

__global__ __launch_bounds__(256, 1)
void attn_kernel() {
    extern __shared__ __align__(128) uint8_t asmem[];
    uint32_t sq = smem_to_u32(asmem);
    uint32_t sk = sq + 36864u;
    uint32_t sv = sk + 36864u;
    int bh = blockIdx.x;
    int b = bh / HH;
    int h = bh - b * HH;
    int tid = threadIdx.x;
    int lane = tid & 31;
    int wid = tid >> 5;

    const __half* qg = g_qkv + (size_t)bh * SS * DH;
    const __half* kg = g_qkv + BHSD + (size_t)bh * SS * DH;
    const __half* vg = g_qkv + 2 * BHSD + (size_t)bh * SS * DH;

    // load Q,K,V into padded smem (row stride 144B)
    #pragma unroll
    for (int i = 0; i < 8; i++) {
        int c = tid + i * 256;          // 0..2047
        int row = c >> 3, q16 = c & 7;
        *(uint4*)(asmem + row * 144 + q16 * 16) =
            *(const uint4*)(qg + row * 64 + q16 * 8);
        *(uint4*)(asmem + 36864 + row * 144 + q16 * 16) =
            *(const uint4*)(kg + row * 64 + q16 * 8);
        *(uint4*)(asmem + 73728 + row * 144 + q16 * 16) =
            *(const uint4*)(vg + row * 64 + q16 * 8);
    }
    __syncthreads();

    int qbi = (wid < 4) ? wid : 11 - wid;   // query block (SMSP balanced)
    int base_r = qbi * 32;

    // Q fragments: [mt][kc][4]
    uint32_t qf[2][4][4];
    #pragma unroll
    for (int mt = 0; mt < 2; mt++)
        #pragma unroll
        for (int kc = 0; kc < 4; kc++)
            ldsm_x4(qf[mt][kc],
                    sq + (uint32_t)(base_r + 16 * mt + (lane & 15)) * 144 +
                    kc * 32 + (lane >> 4) * 16);

    float O[2][8][4];
    #pragma unroll
    for (int mt = 0; mt < 2; mt++)
        #pragma unroll
        for (int nO = 0; nO < 8; nO++)
            #pragma unroll
            for (int t = 0; t < 4; t++) O[mt][nO][t] = 0.f;
    float m[2][2] = {{-1e4f, -1e4f}, {-1e4f, -1e4f}};
    float l[2][2] = {{0.f, 0.f}, {0.f, 0.f}};

    const float SC2 = 0.18033688f;   // 0.125 * log2(e)

    int nkt = 2 * qbi + 2;
    for (int kt = 0; kt < nkt; kt++) {
        // ---- S = Q . K^T (16 keys) ----
        float sacc[2][2][4];
        #pragma unroll
        for (int mt = 0; mt < 2; mt++)
            #pragma unroll
            for (int nt = 0; nt < 2; nt++)
                #pragma unroll
                for (int t = 0; t < 4; t++) sacc[mt][nt][t] = 0.f;
        #pragma unroll
        for (int kc = 0; kc < 4; kc++) {
            uint32_t bk[4];
            ldsm_x4(bk, sk + (uint32_t)(kt * 16 + (lane & 15)) * 144 +
                        kc * 32 + (lane >> 4) * 16);
            uint32_t bb0[2] = { bk[0], bk[2] };
            uint32_t bb1[2] = { bk[1], bk[3] };
            #pragma unroll
            for (int mt = 0; mt < 2; mt++) {
                if (kt <= 2 * qbi + mt) {
                    mma16816(sacc[mt][0], qf[mt][kc], bb0);
                    mma16816(sacc[mt][1], qf[mt][kc], bb1);
                }
            }
        }
        // ---- V fragments (transposed) ----
        uint32_t bv[4][4];
        #pragma unroll
        for (int dp = 0; dp < 4; dp++)
            ldsm_x4t(bv[dp], sv + (uint32_t)(kt * 16 + (lane & 15)) * 144 +
                             dp * 32 + (lane >> 4) * 16);

        #pragma unroll
        for (int mt = 0; mt < 2; mt++) {
            if (kt > 2 * qbi + mt) continue;
            int rbase = base_r + 16 * mt;
            bool diag = (kt == 2 * qbi + mt);
            uint32_t pa[4];
            #pragma unroll
            for (int h2 = 0; h2 < 2; h2++) {
                float v0 = sacc[mt][0][h2 * 2 + 0] * SC2;
                float v1 = sacc[mt][0][h2 * 2 + 1] * SC2;
                float v2 = sacc[mt][1][h2 * 2 + 0] * SC2;
                float v3 = sacc[mt][1][h2 * 2 + 1] * SC2;
                if (diag) {
                    int row = rbase + (lane >> 2) + 8 * h2;
                    int k0 = kt * 16 + 2 * (lane & 3);
                    if (k0 > row)     v0 = -1e4f;
                    if (k0 + 1 > row) v1 = -1e4f;
                    if (k0 + 8 > row) v2 = -1e4f;
                    if (k0 + 9 > row) v3 = -1e4f;
                }
                float cm = fmaxf(fmaxf(v0, v1), fmaxf(v2, v3));
                cm = fmaxf(cm, __shfl_xor_sync(0xffffffffu, cm, 1));
                cm = fmaxf(cm, __shfl_xor_sync(0xffffffffu, cm, 2));
                float mn = fmaxf(m[mt][h2], cm);
                float fct = exp2p(m[mt][h2] - mn);
                m[mt][h2] = mn;
                float p0 = exp2p(v0 - mn);
                float p1 = exp2p(v1 - mn);
                float p2 = exp2p(v2 - mn);
                float p3 = exp2p(v3 - mn);
                l[mt][h2] = l[mt][h2] * fct + (p0 + p1 + p2 + p3);
                #pragma unroll
                for (int nO = 0; nO < 8; nO++) {
                    O[mt][nO][h2 * 2 + 0] *= fct;
                    O[mt][nO][h2 * 2 + 1] *= fct;
                }
                __half2 hp01 = __floats2half2_rn(p0, p1);
                __half2 hp23 = __floats2half2_rn(p2, p3);
                pa[h2]     = *(uint32_t*)&hp01;
                pa[h2 + 2] = *(uint32_t*)&hp23;
            }
            // ---- O += P . V ----
            #pragma unroll
            for (int dp = 0; dp < 4; dp++) {
                uint32_t b0[2] = { bv[dp][0], bv[dp][1] };
                uint32_t b1[2] = { bv[dp][2], bv[dp][3] };
                mma16816(O[mt][2 * dp],     pa, b0);
                mma16816(O[mt][2 * dp + 1], pa, b1);
            }
        }
    }

    // ---- finalize: O /= l, store fp16 ----
    #pragma unroll
    for (int mt = 0; mt < 2; mt++) {
        #pragma unroll
        for (int h2 = 0; h2 < 2; h2++) {
            float lt = l[mt][h2];
            lt += __shfl_xor_sync(0xffffffffu, lt, 1);
            lt += __shfl_xor_sync(0xffffffffu, lt, 2);
            float inv = 1.0f / lt;
            int row = base_r + 16 * mt + (lane >> 2) + 8 * h2;
            __half* ow = g_o + (size_t)(b * SS + row) * EE + h * DH;
            #pragma unroll
            for (int nO = 0; nO < 8; nO++) {
                int col = nO * 8 + 2 * (lane & 3);
                __half2 hv = __floats2half2_rn(O[mt][nO][h2 * 2 + 0] * inv,
                                               O[mt][nO][h2 * 2 + 1] * inv);
                *(__half2*)(ow + col) = hv;
            }
        }
    }
}

// ---------------- host -----------------------------------------------------
extern "C" void kernel_launch(void* const* d_in, const int* in_sizes, int n_in,
                              void* d_out, int out_size) {
    const float* x   = (const float*)d_in[0];
    const float* Wq  = (const float*)d_in[1];
    const float* Wk  = (const float*)d_in[2];
    const float* Wv  = (const float*)d_in[3];
    const float* Wp  = (const float*)d_in[4];
    const float* bp  = (const float*)d_in[5];
    const float* W1  = (const float*)d_in[6];
    const float* b1  = (const float*)d_in[7];
    const float* W2  = (const float*)d_in[8];
    const float* b2  = (const float*)d_in[9];
    const float* g1  = (const float*)d_in[10];
    const float* be1 = (const float*)d_in[11];
    const float* g2  = (const float*)d_in[12];
    const float* be2 = (const float*)d_in[13];
    float* out = (float*)d_out;

    void *hlnv, *qkvv, *ov, *x1v, *h2v, *midv, *wqkvv, *wpv, *w1v, *w2v;
    cudaGetSymbolAddress(&hlnv,  g_hln);
    cudaGetSymbolAddress(&qkvv,  g_qkv);
    cudaGetSymbolAddress(&ov,    g_o);
    cudaGetSymbolAddress(&x1v,   g_x1);
    cudaGetSymbolAddress(&h2v,   g_h2);
    cudaGetSymbolAddress(&midv,  g_mid);
    cudaGetSymbolAddress(&wqkvv, g_wqkv);
    cudaGetSymbolAddress(&wpv,   g_wp);
    cudaGetSymbolAddress(&w1v,   g_w1);
    cudaGetSymbolAddress(&w2v,   g_w2);

    __half* hln  = (__half*)hlnv;
    __half* qkv  = (__half*)qkvv;
    float*  x1   = (float*)x1v;
    __half* h2   = (__half*)h2v;
    __half* mid  = (__half*)midv;
    __half* wqkv = (__half*)wqkvv;
    __half* wp   = (__half*)wpv;
    __half* w1   = (__half*)w1v;
    __half* w2   = (__half*)w2v;
    __half* o    = (__half*)ov;

    cudaFuncSetAttribute(mma_gemm, cudaFuncAttributeMaxDynamicSharedMemorySize, GSMEM);
    cudaFuncSetAttribute(attn_kernel, cudaFuncAttributeMaxDynamicSharedMemorySize,
                         ATTN_SMEM);

    // weight packing (fp16)
    pack_qkv_kernel<<<(1152 * 384 + 255) / 256, 256>>>(Wq, Wk, Wv);
    pack_gen_kernel<<<(384 * 384 + 255) / 256, 256>>>(Wp, wp, 384, 384, 384);
    pack_gen_kernel<<<(1536 * 384 + 255) / 256, 256>>>(W1, w1, 1536, 384, 1536);
    pack_gen_kernel<<<(384 * 1536 + 255) / 256, 256>>>(W2, w2, 384, 1536, 384);
    // LN1 (warp-per-row)
    ln_kernel<<<MM / 4, 128>>>(x, g1, be1, hln);
    // QKV projection (scatter into [3][B,H,S,D] fp16)
    mma_gemm<<<dim3(9, 512), 256, GSMEM>>>(
        hln, wqkv, qkv, nullptr, nullptr, 384, 1152, 0);
    // causal attention (flash, tensor-core)
    attn_kernel<<<BB * HH, 256, ATTN_SMEM>>>();
    // out projection + residual: x1 = x + o@Wp + bp
    mma_gemm<<<dim3(3, 512), 256, GSMEM>>>(
        o, wp, x1, bp, x, 384, 384, 1);
    // LN2 (warp-per-row)
    ln_kernel<<<MM / 4, 128>>>(x1, g2, be2, h2);
    // FFN1 + relu -> fp16
    mma_gemm<<<dim3(12, 512), 256, GSMEM>>>(
        h2, w1, mid, b1, nullptr, 384, 1536, 2);
    // FFN2 + residual -> out (N=384 -> 3 tiles of 128)
    mma_gemm<<<dim3(3, 512), 256, GSMEM>>>(
        mid, w2, out, b2, x1, 1536, 384, 3);
}